// round 3
// baseline (speedup 1.0000x reference)
#include <cuda_runtime.h>

// ---------------------------------------------------------------------------
// MultiscaleDecomposedConv1D
//   B=8, S=8, T=4096, C_IN=128, C_OUT=256, KSIZE_T=9, KSIZE_S=3
//   Stage A: synthesize per-scale time kernels W[s][tap][i][o] from Fourier coeffs
//   Stage B: scale-axis 3-tap conv (edge-repeat pad) -> xs
//   Stage C: per-(b,s) time conv as implicit GEMM (M=4096, N=256, K=1152),
//            fp32 via packed fma.rn.f32x2 (FFMA2) for full-rate fp32.
// ---------------------------------------------------------------------------

#define PI_F 3.14159274101257324f

// Scratch (device globals: allocation-free per harness rules)
__device__ float g_W[8 * 9 * 128 * 256];            // 9.4 MB synthesized kernels
__device__ float g_xs[(size_t)8 * 8 * 4096 * 128];  // 128 MB scale-conv output

__constant__ float c_scales[8] = {-1.5f, -1.0f, -0.5f, 0.0f, 0.5f, 1.0f, 1.5f, 2.0f};

// ---------------------------------------------------------------------------
// packed f32x2 helpers
// ---------------------------------------------------------------------------
__device__ __forceinline__ unsigned long long ffma2(unsigned long long a,
                                                    unsigned long long b,
                                                    unsigned long long c) {
    unsigned long long d;
    asm("fma.rn.f32x2 %0, %1, %2, %3;" : "=l"(d) : "l"(a), "l"(b), "l"(c));
    return d;
}
__device__ __forceinline__ unsigned long long splat2(float a) {
    unsigned long long r;
    asm("mov.b64 %0, {%1, %1};" : "=l"(r) : "f"(a));
    return r;
}
__device__ __forceinline__ unsigned long long pack2(float lo, float hi) {
    unsigned long long r;
    asm("mov.b64 %0, {%1, %2};" : "=l"(r) : "f"(lo), "f"(hi));
    return r;
}
__device__ __forceinline__ void unpack2(unsigned long long v, float& lo, float& hi) {
    asm("mov.b64 {%0, %1}, %2;" : "=f"(lo), "=f"(hi) : "l"(v));
}

// ---------------------------------------------------------------------------
// Stage A: kernel synthesis
//   W[s][tap][i][o] = 2^alpha * mask(|u|<=1) * sum_c basis_c(u) * coeffs[c][i][o]
//   u = ((tap-4)/4) * 2^{-alpha}; basis = {1, sin(pi u), cos(pi u), sin(2pi u), cos(2pi u)}
//   grid: 72 blocks (s*9+tap), 256 threads (o), loop i
// ---------------------------------------------------------------------------
__global__ void wsynth_kernel(const float* __restrict__ coeffs) {
    int st  = blockIdx.x;         // s*9 + tap
    int s   = st / 9;
    int tap = st % 9;
    int o   = threadIdx.x;

    float alpha = c_scales[s];
    float u     = ((float)(tap - 4) * 0.25f) * exp2f(-alpha);
    float gain  = exp2f(alpha) * ((fabsf(u) <= 1.0f) ? 1.0f : 0.0f);

    float b1 = sinf(PI_F * u);
    float b2 = cosf(PI_F * u);
    float f2 = PI_F * 2.0f;
    float b3 = sinf(f2 * u);
    float b4 = cosf(f2 * u);

    const int KIO = 128 * 256;
    size_t base = (size_t)st * KIO + o;
    #pragma unroll 4
    for (int i = 0; i < 128; ++i) {
        const float* cp = coeffs + i * 256 + o;
        float acc = cp[0]            // basis_0 = cos(0) = 1
                  + b1 * cp[1 * KIO]
                  + b2 * cp[2 * KIO]
                  + b3 * cp[3 * KIO]
                  + b4 * cp[4 * KIO];
        g_W[base + (size_t)i * 256] = gain * acc;
    }
}

// ---------------------------------------------------------------------------
// Stage B: scale-axis conv (edge-repeat pad on S axis)
//   xs[b,s,t,c] = w0*x[b,max(s-1,0)] + w1*x[b,s] + w2*x[b,min(s+1,7)]
//   w_j from coeffs_scale with basis {1, sin(pi u), cos(pi u)}, u in {-1,0,1}
//   one float4 per thread; 8,388,608 float4 total
// ---------------------------------------------------------------------------
__global__ void sconv_kernel(const float* __restrict__ x,
                             const float* __restrict__ cs) {
    int idx = blockIdx.x * blockDim.x + threadIdx.x;  // float4 index

    float sn = sinf(PI_F);    // sin(pi) residual (matches fp32 reference)
    float cn = cosf(PI_F);    // ~ -1
    float c0 = cs[0], c1 = cs[1], c2 = cs[2];
    float w0 = c0 - c1 * sn + c2 * cn;   // u = -1: sin(-pi) = -sin(pi)
    float w1 = c0 + c2;                  // u =  0: sin=0, cos=1
    float w2 = c0 + c1 * sn + c2 * cn;   // u = +1

    int c4 = idx & 31;
    int t  = (idx >> 5) & 4095;
    int s  = (idx >> 17) & 7;
    int b  = idx >> 20;
    int sm = max(s - 1, 0);
    int sp = min(s + 1, 7);

    const size_t rowstride = 4096 * 32;  // float4 per (b,s) row
    size_t bbase = (size_t)b * 8 * rowstride + (size_t)t * 32 + c4;

    const float4* xp = reinterpret_cast<const float4*>(x);
    float4 a = xp[bbase + (size_t)sm * rowstride];
    float4 m = xp[bbase + (size_t)s  * rowstride];
    float4 p = xp[bbase + (size_t)sp * rowstride];

    float4 r;
    r.x = w0 * a.x + w1 * m.x + w2 * p.x;
    r.y = w0 * a.y + w1 * m.y + w2 * p.y;
    r.z = w0 * a.z + w1 * m.z + w2 * p.z;
    r.w = w0 * a.w + w1 * m.w + w2 * p.w;

    reinterpret_cast<float4*>(g_xs)[bbase + (size_t)s * rowstride] = r;
}

// ---------------------------------------------------------------------------
// Stage C: time conv as implicit GEMM
//   out[bs, t, o] = sum_{tap,i} xs[bs, t+tap-4, i] * W[s][tap][i][o]
//   block: 256 thr, tile M=64 (time) x N=128 (out-ch)
//   warp w -> rows [8w, 8w+8); lane -> 4 consecutive o (2 packed f32x2 accums)
//   A tile (72x128) resident in smem for whole K loop (broadcast reads)
//   B streamed in 8x128 chunks (conflict-free LDS.128)
// ---------------------------------------------------------------------------
__global__ void __launch_bounds__(256, 2)
tconv_kernel(float* __restrict__ out) {
    __shared__ float sA[72][128];
    __shared__ float sB[8][128];

    int tid  = threadIdx.x;
    int bs   = blockIdx.z;           // b*8 + s
    int sIdx = bs & 7;
    int t0   = blockIdx.x * 64;
    int ob   = blockIdx.y * 128;

    // ---- load A tile (time rows t0-4 .. t0+67, zero-padded) ----
    const float* xsp = g_xs + (size_t)bs * (4096 * 128);
    for (int l = tid; l < 72 * 32; l += 256) {
        int row = l >> 5;
        int c4  = l & 31;
        int t   = t0 - 4 + row;
        float4 v = make_float4(0.f, 0.f, 0.f, 0.f);
        if (t >= 0 && t < 4096)
            v = *reinterpret_cast<const float4*>(xsp + (size_t)t * 128 + c4 * 4);
        *reinterpret_cast<float4*>(&sA[row][c4 * 4]) = v;
    }

    int warp  = tid >> 5;
    int lane  = tid & 31;
    int mbase = warp * 8;
    int nb    = lane * 4;

    unsigned long long acc[8][2];
    #pragma unroll
    for (int m = 0; m < 8; ++m) { acc[m][0] = 0ull; acc[m][1] = 0ull; }

    const float* Wbase = g_W + (size_t)(sIdx * 9) * (128 * 256) + ob;

    for (int tap = 0; tap < 9; ++tap) {
        #pragma unroll 1
        for (int ic = 0; ic < 128; ic += 8) {
            __syncthreads();  // protect sB readers from previous chunk (and sA fill, 1st iter)
            // load B chunk: rows k = tap*128+ic .. +7, cols [ob, ob+128)
            float4 wv = *reinterpret_cast<const float4*>(
                Wbase + (size_t)(tap * 128 + ic + warp) * 256 + nb);
            *reinterpret_cast<float4*>(&sB[warp][nb]) = wv;
            __syncthreads();

            const float* ap = &sA[mbase + tap][ic];
            #pragma unroll
            for (int kk4 = 0; kk4 < 8; kk4 += 4) {
                // B pairs for 4 k-steps (LDS.128, conflict-free; pair via reg pack)
                unsigned long long bq0[4], bq1[4];
                #pragma unroll
                for (int j = 0; j < 4; ++j) {
                    float4 bv = *reinterpret_cast<const float4*>(&sB[kk4 + j][nb]);
                    bq0[j] = pack2(bv.x, bv.y);
                    bq1[j] = pack2(bv.z, bv.w);
                }
                #pragma unroll
                for (int m = 0; m < 8; ++m) {
                    float4 av = *reinterpret_cast<const float4*>(ap + m * 128 + kk4);
                    unsigned long long a0 = splat2(av.x);
                    unsigned long long a1 = splat2(av.y);
                    unsigned long long a2 = splat2(av.z);
                    unsigned long long a3 = splat2(av.w);
                    acc[m][0] = ffma2(a0, bq0[0], acc[m][0]);
                    acc[m][1] = ffma2(a0, bq1[0], acc[m][1]);
                    acc[m][0] = ffma2(a1, bq0[1], acc[m][0]);
                    acc[m][1] = ffma2(a1, bq1[1], acc[m][1]);
                    acc[m][0] = ffma2(a2, bq0[2], acc[m][0]);
                    acc[m][1] = ffma2(a2, bq1[2], acc[m][1]);
                    acc[m][0] = ffma2(a3, bq0[3], acc[m][0]);
                    acc[m][1] = ffma2(a3, bq1[3], acc[m][1]);
                }
            }
        }
    }

    // ---- epilogue: float4 stores, fully coalesced ----
    float* op = out + ((size_t)bs * 4096 + t0 + mbase) * 256 + ob + nb;
    #pragma unroll
    for (int m = 0; m < 8; ++m) {
        float4 r;
        unpack2(acc[m][0], r.x, r.y);
        unpack2(acc[m][1], r.z, r.w);
        *reinterpret_cast<float4*>(op + (size_t)m * 256) = r;
    }
}

// ---------------------------------------------------------------------------
// launch
//   d_in[0]: x_in          (8,8,4096,128) f32
//   d_in[1]: coeffs        (5,128,256)    f32
//   d_in[2]: coeffs_scale  (3,1,1)        f32
//   d_out  : (8,8,4096,256) f32
// ---------------------------------------------------------------------------
extern "C" void kernel_launch(void* const* d_in, const int* in_sizes, int n_in,
                              void* d_out, int out_size) {
    const float* x      = (const float*)d_in[0];
    const float* coeffs = (const float*)d_in[1];
    const float* cs     = (const float*)d_in[2];
    float* out          = (float*)d_out;

    wsynth_kernel<<<72, 256>>>(coeffs);
    sconv_kernel<<<32768, 256>>>(x, cs);
    tconv_kernel<<<dim3(64, 2, 64), 256>>>(out);
}

// round 5
// speedup vs baseline: 3.2465x; 3.2465x over previous
#include <cuda_runtime.h>
#include <cuda_bf16.h>
#include <cstdint>

#define PI_F 3.14159274101257324f

// ---------------- device scratch (static: allocation-free) ----------------
__device__ float         g_xs[(size_t)64 * 4096 * 128];   // 134 MB fp32 scale-conv
__device__ __nv_bfloat16 g_yh[(size_t)64 * 4096 * 640];   // 336 MB y hi
__device__ __nv_bfloat16 g_yl[(size_t)64 * 4096 * 640];   // 336 MB y lo
__device__ __nv_bfloat16 g_Bh[256 * 640];                 // C^T hi [n][k]
__device__ __nv_bfloat16 g_Bl[256 * 640];                 // C^T lo

__constant__ float c_scales[8] = {-1.5f, -1.0f, -0.5f, 0.0f, 0.5f, 1.0f, 1.5f, 2.0f};

// ---------------- helpers ----------------
__device__ __forceinline__ uint32_t smem_u32(const void* p) {
    uint32_t a;
    asm("{ .reg .u64 t; cvta.to.shared.u64 t, %1; cvt.u32.u64 %0, t; }" : "=r"(a) : "l"(p));
    return a;
}
#define CP16(dst, src) \
    asm volatile("cp.async.cg.shared.global [%0], [%1], 16;" :: "r"(dst), "l"(src) : "memory")
#define CP_COMMIT() asm volatile("cp.async.commit_group;" ::: "memory")
#define CP_WAIT1()  asm volatile("cp.async.wait_group 1;" ::: "memory")
#define CP_WAIT0()  asm volatile("cp.async.wait_group 0;" ::: "memory")

#define MMA(d, a, b) \
    asm volatile("mma.sync.aligned.m16n8k16.row.col.f32.bf16.bf16.f32 " \
                 "{%0,%1,%2,%3}, {%4,%5,%6,%7}, {%8,%9}, {%0,%1,%2,%3};" \
                 : "+f"((d)[0]), "+f"((d)[1]), "+f"((d)[2]), "+f"((d)[3]) \
                 : "r"((a)[0]), "r"((a)[1]), "r"((a)[2]), "r"((a)[3]), \
                   "r"((b)[0]), "r"((b)[1]))

__device__ __forceinline__ void split_bf16(float v, __nv_bfloat16& h, __nv_bfloat16& l) {
    h = __float2bfloat16_rn(v);
    l = __float2bfloat16_rn(v - __bfloat162float(h));
}

// ---------------------------------------------------------------------------
// prep: B = C^T split to bf16 hi/lo.  coeffs flat: [(c*128+i)*256 + o]
// ---------------------------------------------------------------------------
__global__ void prep_kernel(const float* __restrict__ coeffs) {
    int idx = blockIdx.x * 256 + threadIdx.x;        // 163840 total
    int k = idx % 640, n = idx / 640;
    float w = coeffs[k * 256 + n];
    __nv_bfloat16 h, l;
    split_bf16(w, h, l);
    g_Bh[n * 640 + k] = h;
    g_Bl[n * 640 + k] = l;
}

// ---------------------------------------------------------------------------
// Stage B: scale-axis 3-tap conv (edge-repeat pad), fp32 -> g_xs
// ---------------------------------------------------------------------------
__global__ void sconv_kernel(const float* __restrict__ x, const float* __restrict__ cs) {
    int idx = blockIdx.x * blockDim.x + threadIdx.x;  // float4 index

    float sn = sinf(PI_F), cn = cosf(PI_F);
    float c0 = cs[0], c1 = cs[1], c2 = cs[2];
    float w0 = c0 - c1 * sn + c2 * cn;
    float w1 = c0 + c2;
    float w2 = c0 + c1 * sn + c2 * cn;

    int c4 = idx & 31, t = (idx >> 5) & 4095, s = (idx >> 17) & 7, b = idx >> 20;
    int sm = max(s - 1, 0), sp = min(s + 1, 7);
    const size_t rowstride = 4096 * 32;
    size_t bbase = (size_t)b * 8 * rowstride + (size_t)t * 32 + c4;

    const float4* xp = reinterpret_cast<const float4*>(x);
    float4 a = xp[bbase + (size_t)sm * rowstride];
    float4 m = xp[bbase + (size_t)s * rowstride];
    float4 p = xp[bbase + (size_t)sp * rowstride];

    float4 r;
    r.x = w0 * a.x + w1 * m.x + w2 * p.x;
    r.y = w0 * a.y + w1 * m.y + w2 * p.y;
    r.z = w0 * a.z + w1 * m.z + w2 * p.z;
    r.w = w0 * a.w + w1 * m.w + w2 * p.w;

    reinterpret_cast<float4*>(g_xs)[bbase + (size_t)s * rowstride] = r;
}

// ---------------------------------------------------------------------------
// Stage Y: y_c[m,i] = sum_tap w[s][c][tap] * xs[m+tap-4, i]  (zero pad in t)
//   grid (32 t-tiles, 64 bs), 256 thr, dyn smem 136*128 fp32
//   writes bf16 hi/lo split, k-layout c*128+i
// ---------------------------------------------------------------------------
__global__ void __launch_bounds__(256) yconv_kernel() {
    extern __shared__ float sx[];            // [136][128]
    __shared__ float sw[5][9];
    int bs = blockIdx.y, s = bs & 7, t0 = blockIdx.x * 128;
    int tid = threadIdx.x;

    if (tid < 45) {
        int c = tid / 9, tap = tid % 9;
        float alpha = c_scales[s];
        float u = ((float)(tap - 4) * 0.25f) * exp2f(-alpha);
        float mask = (fabsf(u) <= 1.0f) ? 1.0f : 0.0f;
        float freq = (float)((c + 1) / 2);
        float arg = PI_F * freq * u;
        float b = (c & 1) ? sinf(arg) : cosf(arg);
        sw[c][tap] = exp2f(alpha) * mask * b;
    }

    const float4* xp = reinterpret_cast<const float4*>(g_xs + (size_t)bs * 4096 * 128);
    for (int l = tid; l < 136 * 32; l += 256) {
        int row = l >> 5, c4 = l & 31;
        int t = t0 - 4 + row;
        float4 v = make_float4(0.f, 0.f, 0.f, 0.f);
        if (t >= 0 && t < 4096) v = xp[(size_t)t * 32 + c4];
        *reinterpret_cast<float4*>(&sx[row * 128 + c4 * 4]) = v;
    }
    __syncthreads();

    for (int it = 0; it < 64; ++it) {
        int idx = tid + it * 256;
        int i = idx & 127, tl = idx >> 7;
        float v[9];
        #pragma unroll
        for (int tap = 0; tap < 9; ++tap) v[tap] = sx[(tl + tap) * 128 + i];
        size_t mbase = ((size_t)bs * 4096 + t0 + tl) * 640 + i;
        #pragma unroll
        for (int c = 0; c < 5; ++c) {
            float acc = 0.f;
            #pragma unroll
            for (int tap = 0; tap < 9; ++tap) acc += sw[c][tap] * v[tap];
            __nv_bfloat16 h, l;
            split_bf16(acc, h, l);
            g_yh[mbase + c * 128] = h;
            g_yl[mbase + c * 128] = l;
        }
    }
}

// ---------------------------------------------------------------------------
// GEMM: out[m,n] = sum_k y[m,k] * C[k,n], M=262144, N=256, K=640
//   bf16 3-pass (AhBh + AlBh + AhBl), fp32 accum via mma.sync m16n8k16
//   CTA 128x128, 8 warps (warp 64x32), BK=32, 3-stage cp.async pipeline
//   smem rows padded to 40 bf16 (80B): 20-word stride -> conflict-free lds
// ---------------------------------------------------------------------------
#define STG 40960                 // stage stride bytes (4 arrays * 128*80)
#define AOFF_L 10240
#define BOFF_H 20480
#define BOFF_L 30720

__global__ void __launch_bounds__(256, 1) gemm_kernel(float* __restrict__ out) {
    extern __shared__ char smem[];
    uint32_t sbase = smem_u32(smem);

    int tid = threadIdx.x, wid = tid >> 5, lane = tid & 31;
    int n0 = blockIdx.x * 128;
    size_t m0 = (size_t)blockIdx.y * 128;
    int warp_m = wid & 1, warp_n = wid >> 1;

    const __nv_bfloat16* gAh = g_yh + m0 * 640;
    const __nv_bfloat16* gAl = g_yl + m0 * 640;
    const __nv_bfloat16* gBh = g_Bh + (size_t)n0 * 640;
    const __nv_bfloat16* gBl = g_Bl + (size_t)n0 * 640;

    int crow = tid >> 1;                 // 0..127
    int cc = (tid & 1) << 1;             // chunk base 0 / 2

    // producer: 8 x 16B per stage per thread
    #define ISSUE(sg, kblk) do {                                                   \
        uint32_t sb = sbase + (sg) * STG + crow * 80 + cc * 16;                    \
        size_t so = (size_t)crow * 640 + (kblk) * 32 + cc * 8;                     \
        CP16(sb,               gAh + so);  CP16(sb + 16,          gAh + so + 8);   \
        CP16(sb + AOFF_L,      gAl + so);  CP16(sb + AOFF_L + 16, gAl + so + 8);   \
        CP16(sb + BOFF_H,      gBh + so);  CP16(sb + BOFF_H + 16, gBh + so + 8);   \
        CP16(sb + BOFF_L,      gBl + so);  CP16(sb + BOFF_L + 16, gBl + so + 8);   \
    } while (0)

    float acc[4][4][4];
    #pragma unroll
    for (int a = 0; a < 4; ++a)
        #pragma unroll
        for (int b = 0; b < 4; ++b)
            #pragma unroll
            for (int c = 0; c < 4; ++c) acc[a][b][c] = 0.f;

    ISSUE(0, 0); CP_COMMIT();
    ISSUE(1, 1); CP_COMMIT();

    int r = lane >> 2, q = lane & 3;

    for (int kb = 0; kb < 20; ++kb) {
        if (kb < 18) CP_WAIT1(); else CP_WAIT0();
        __syncthreads();
        if (kb + 2 < 20) { ISSUE((kb + 2) % 3, kb + 2); CP_COMMIT(); }

        int sg = kb % 3;
        const __nv_bfloat16* pAh = (const __nv_bfloat16*)(smem + sg * STG);
        const __nv_bfloat16* pAl = (const __nv_bfloat16*)(smem + sg * STG + AOFF_L);
        const __nv_bfloat16* pBh = (const __nv_bfloat16*)(smem + sg * STG + BOFF_H);
        const __nv_bfloat16* pBl = (const __nv_bfloat16*)(smem + sg * STG + BOFF_L);

        #pragma unroll
        for (int h = 0; h < 2; ++h) {
            int kb16 = h * 16 + q * 2;
            uint32_t Ah[4][4], Al[4][4], Bh[4][2], Bl[4][2];
            #pragma unroll
            for (int mf = 0; mf < 4; ++mf) {
                int row = warp_m * 64 + mf * 16 + r;
                Ah[mf][0] = *(const uint32_t*)(pAh + row * 40 + kb16);
                Ah[mf][1] = *(const uint32_t*)(pAh + (row + 8) * 40 + kb16);
                Ah[mf][2] = *(const uint32_t*)(pAh + row * 40 + kb16 + 8);
                Ah[mf][3] = *(const uint32_t*)(pAh + (row + 8) * 40 + kb16 + 8);
                Al[mf][0] = *(const uint32_t*)(pAl + row * 40 + kb16);
                Al[mf][1] = *(const uint32_t*)(pAl + (row + 8) * 40 + kb16);
                Al[mf][2] = *(const uint32_t*)(pAl + row * 40 + kb16 + 8);
                Al[mf][3] = *(const uint32_t*)(pAl + (row + 8) * 40 + kb16 + 8);
            }
            #pragma unroll
            for (int nf = 0; nf < 4; ++nf) {
                int n = warp_n * 32 + nf * 8 + r;
                Bh[nf][0] = *(const uint32_t*)(pBh + n * 40 + kb16);
                Bh[nf][1] = *(const uint32_t*)(pBh + n * 40 + kb16 + 8);
                Bl[nf][0] = *(const uint32_t*)(pBl + n * 40 + kb16);
                Bl[nf][1] = *(const uint32_t*)(pBl + n * 40 + kb16 + 8);
            }
            #pragma unroll
            for (int mf = 0; mf < 4; ++mf)
                #pragma unroll
                for (int nf = 0; nf < 4; ++nf) {
                    MMA(acc[mf][nf], Ah[mf], Bh[nf]);
                    MMA(acc[mf][nf], Al[mf], Bh[nf]);
                    MMA(acc[mf][nf], Ah[mf], Bl[nf]);
                }
        }
        __syncthreads();
    }

    // epilogue
    size_t mr0 = m0 + warp_m * 64;
    int nc0 = n0 + warp_n * 32;
    #pragma unroll
    for (int mf = 0; mf < 4; ++mf) {
        size_t row = mr0 + mf * 16 + r;
        #pragma unroll
        for (int nf = 0; nf < 4; ++nf) {
            int col = nc0 + nf * 8 + q * 2;
            *reinterpret_cast<float2*>(out + row * 256 + col) =
                make_float2(acc[mf][nf][0], acc[mf][nf][1]);
            *reinterpret_cast<float2*>(out + (row + 8) * 256 + col) =
                make_float2(acc[mf][nf][2], acc[mf][nf][3]);
        }
    }
}

// ---------------------------------------------------------------------------
extern "C" void kernel_launch(void* const* d_in, const int* in_sizes, int n_in,
                              void* d_out, int out_size) {
    const float* x = (const float*)d_in[0];
    const float* coeffs = (const float*)d_in[1];
    const float* cs = (const float*)d_in[2];
    float* out = (float*)d_out;

    cudaFuncSetAttribute(yconv_kernel, cudaFuncAttributeMaxDynamicSharedMemorySize, 69632);
    cudaFuncSetAttribute(gemm_kernel, cudaFuncAttributeMaxDynamicSharedMemorySize, 122880);

    prep_kernel<<<640, 256>>>(coeffs);
    sconv_kernel<<<32768, 256>>>(x, cs);
    yconv_kernel<<<dim3(32, 64), 256, 69632>>>();
    gemm_kernel<<<dim3(2, 2048), 256, 122880>>>(out);
}

// round 7
// speedup vs baseline: 7.3869x; 2.2754x over previous
#include <cuda_runtime.h>
#include <cuda_fp16.h>
#include <cstdint>

#define PI_F 3.14159274101257324f

// ---------------- device scratch (static: allocation-free) ----------------
__device__ float  g_xs[(size_t)64 * 4096 * 128];   // 134 MB fp32 scale-conv
__device__ __half g_y[(size_t)64 * 4096 * 640];    // 336 MB y (fp16)
__device__ __half g_B[256 * 640];                  // C^T fp16 [n][k]

__constant__ float c_scales[8] = {-1.5f, -1.0f, -0.5f, 0.0f, 0.5f, 1.0f, 1.5f, 2.0f};

// ---------------- helpers ----------------
__device__ __forceinline__ uint32_t smem_u32(const void* p) {
    uint32_t a;
    asm("{ .reg .u64 t; cvta.to.shared.u64 t, %1; cvt.u32.u64 %0, t; }" : "=r"(a) : "l"(p));
    return a;
}
#define CP16(dst, src) \
    asm volatile("cp.async.cg.shared.global [%0], [%1], 16;" :: "r"(dst), "l"(src) : "memory")
#define CP_COMMIT() asm volatile("cp.async.commit_group;" ::: "memory")
#define CP_WAITN(n) asm volatile("cp.async.wait_group %0;" :: "n"(n) : "memory")

#define LDSM4(r, addr) \
    asm volatile("ldmatrix.sync.aligned.m8n8.x4.shared.b16 {%0,%1,%2,%3}, [%4];" \
                 : "=r"((r)[0]), "=r"((r)[1]), "=r"((r)[2]), "=r"((r)[3]) : "r"(addr))

#define MMAH(d, a, b0, b1) \
    asm volatile("mma.sync.aligned.m16n8k16.row.col.f32.f16.f16.f32 " \
                 "{%0,%1,%2,%3}, {%4,%5,%6,%7}, {%8,%9}, {%0,%1,%2,%3};" \
                 : "+f"((d)[0]), "+f"((d)[1]), "+f"((d)[2]), "+f"((d)[3]) \
                 : "r"((a)[0]), "r"((a)[1]), "r"((a)[2]), "r"((a)[3]), \
                   "r"(b0), "r"(b1))

// ---------------------------------------------------------------------------
// prep: B = C^T fp16.  coeffs flat: [(c*128+i)*256 + o] -> g_B[o][k]
// ---------------------------------------------------------------------------
__global__ void prep_kernel(const float* __restrict__ coeffs) {
    int k = blockIdx.x;          // 640
    int n = threadIdx.x;         // 256
    g_B[n * 640 + k] = __float2half_rn(coeffs[k * 256 + n]);
}

// ---------------------------------------------------------------------------
// Stage B: scale-axis 3-tap conv (edge-repeat pad), fp32 -> g_xs
// ---------------------------------------------------------------------------
__global__ void sconv_kernel(const float* __restrict__ x, const float* __restrict__ cs) {
    int idx = blockIdx.x * blockDim.x + threadIdx.x;  // float4 index

    float sn = sinf(PI_F), cn = cosf(PI_F);
    float c0 = cs[0], c1 = cs[1], c2 = cs[2];
    float w0 = c0 - c1 * sn + c2 * cn;
    float w1 = c0 + c2;
    float w2 = c0 + c1 * sn + c2 * cn;

    int c4 = idx & 31, t = (idx >> 5) & 4095, s = (idx >> 17) & 7, b = idx >> 20;
    int sm = max(s - 1, 0), sp = min(s + 1, 7);
    const size_t rowstride = 4096 * 32;
    size_t bbase = (size_t)b * 8 * rowstride + (size_t)t * 32 + c4;

    const float4* xp = reinterpret_cast<const float4*>(x);
    float4 a = xp[bbase + (size_t)sm * rowstride];
    float4 m = xp[bbase + (size_t)s * rowstride];
    float4 p = xp[bbase + (size_t)sp * rowstride];

    float4 r;
    r.x = w0 * a.x + w1 * m.x + w2 * p.x;
    r.y = w0 * a.y + w1 * m.y + w2 * p.y;
    r.z = w0 * a.z + w1 * m.z + w2 * p.z;
    r.w = w0 * a.w + w1 * m.w + w2 * p.w;

    reinterpret_cast<float4*>(g_xs)[bbase + (size_t)s * rowstride] = r;
}

// ---------------------------------------------------------------------------
// Stage Y: y_c[m,i] = sum_tap w[s][c][tap] * xs[m+tap-4, i]  (zero pad in t)
//   grid (32 t-tiles, 64 bs), 256 thr; fp16 output, half2 stores
// ---------------------------------------------------------------------------
__global__ void __launch_bounds__(256) yconv_kernel() {
    extern __shared__ float sx[];            // [136][128]
    __shared__ float sw[5][9];
    int bs = blockIdx.y, s = bs & 7, t0 = blockIdx.x * 128;
    int tid = threadIdx.x;

    if (tid < 45) {
        int c = tid / 9, tap = tid % 9;
        float alpha = c_scales[s];
        float u = ((float)(tap - 4) * 0.25f) * exp2f(-alpha);
        float mask = (fabsf(u) <= 1.0f) ? 1.0f : 0.0f;
        float freq = (float)((c + 1) / 2);
        float arg = PI_F * freq * u;
        float b = (c & 1) ? sinf(arg) : cosf(arg);
        sw[c][tap] = exp2f(alpha) * mask * b;
    }

    const float4* xp = reinterpret_cast<const float4*>(g_xs + (size_t)bs * 4096 * 128);
    for (int l = tid; l < 136 * 32; l += 256) {
        int row = l >> 5, c4 = l & 31;
        int t = t0 - 4 + row;
        float4 v = make_float4(0.f, 0.f, 0.f, 0.f);
        if (t >= 0 && t < 4096) v = xp[(size_t)t * 32 + c4];
        *reinterpret_cast<float4*>(&sx[row * 128 + c4 * 4]) = v;
    }
    __syncthreads();

    for (int it = 0; it < 32; ++it) {
        int idx = tid + it * 256;          // 8192: (tl, i-pair)
        int ip = idx & 63, tl = idx >> 6;
        int i0 = ip * 2;
        float v0[9], v1[9];
        #pragma unroll
        for (int tap = 0; tap < 9; ++tap) {
            v0[tap] = sx[(tl + tap) * 128 + i0];
            v1[tap] = sx[(tl + tap) * 128 + i0 + 1];
        }
        size_t mbase = ((size_t)bs * 4096 + t0 + tl) * 640 + i0;
        #pragma unroll
        for (int c = 0; c < 5; ++c) {
            float a0 = 0.f, a1 = 0.f;
            #pragma unroll
            for (int tap = 0; tap < 9; ++tap) {
                a0 += sw[c][tap] * v0[tap];
                a1 += sw[c][tap] * v1[tap];
            }
            *reinterpret_cast<__half2*>(&g_y[mbase + c * 128]) =
                __floats2half2_rn(a0, a1);
        }
    }
}

// ---------------------------------------------------------------------------
// GEMM: out[m,n] = sum_k y[m,k] * B[n,k], M=262144, N=256, K=640
//   1-pass fp16 mma.sync m16n8k16, fp32 accum
//   CTA 128x256, 512 thr (16 warps, warp 32x64), BK=32, 4-stage cp.async
//   smem rows pitch 80B (conflict-free ldmatrix), ldmatrix.x4 fragments
// ---------------------------------------------------------------------------
#define STG 30720                 // stage stride: A 10240 + B 20480

__global__ void __launch_bounds__(512, 1) gemm_kernel(float* __restrict__ out) {
    extern __shared__ char smem[];
    uint32_t sbase = smem_u32(smem);

    int tid = threadIdx.x, wid = tid >> 5, lane = tid & 31;
    size_t m0 = (size_t)blockIdx.x * 128;
    int warp_m = wid & 3, warp_n = wid >> 2;

    const __half* gA = g_y + m0 * 640;

    // producer: 3 x 16B chunks per thread per stage
    int arow = tid >> 2, ac4 = tid & 3;           // A: 512 chunks
    int brow0 = tid >> 2, bc40 = tid & 3;         // B: chunks tid, tid+512
    int brow1 = 128 + (tid >> 2);
    #define ISSUE(sg, kblk) do {                                                  \
        uint32_t st = sbase + (sg) * STG;                                         \
        CP16(st + arow * 80 + ac4 * 16,                                           \
             gA + (size_t)arow * 640 + (kblk) * 32 + ac4 * 8);                    \
        CP16(st + 10240 + brow0 * 80 + bc40 * 16,                                 \
             g_B + brow0 * 640 + (kblk) * 32 + bc40 * 8);                         \
        CP16(st + 10240 + brow1 * 80 + bc40 * 16,                                 \
             g_B + brow1 * 640 + (kblk) * 32 + bc40 * 8);                         \
    } while (0)

    float acc[2][8][4];
    #pragma unroll
    for (int mf = 0; mf < 2; ++mf)
        #pragma unroll
        for (int nf = 0; nf < 8; ++nf)
            #pragma unroll
            for (int c = 0; c < 4; ++c) acc[mf][nf][c] = 0.f;

    ISSUE(0, 0); CP_COMMIT();
    ISSUE(1, 1); CP_COMMIT();
    ISSUE(2, 2); CP_COMMIT();

    // ldmatrix lane-base offsets
    uint32_t aoff = (uint32_t)(warp_m * 32 + (lane & 15)) * 80 + ((lane >> 4) & 1) * 16;
    uint32_t boff = (uint32_t)(warp_n * 64 + (lane & 7) + ((lane >> 4) & 1) * 8) * 80 +
                    ((lane >> 3) & 1) * 16;

    for (int kb = 0; kb < 20; ++kb) {
        if (kb < 17) CP_WAITN(2);
        else if (kb == 17) CP_WAITN(2);
        else if (kb == 18) CP_WAITN(1);
        else CP_WAITN(0);
        __syncthreads();
        if (kb + 3 < 20) { ISSUE((kb + 3) & 3, kb + 3); CP_COMMIT(); }

        uint32_t sA = sbase + (kb & 3) * STG;
        uint32_t sB = sA + 10240;

        #pragma unroll
        for (int h = 0; h < 2; ++h) {
            uint32_t Af[2][4], Bf[4][4];
            #pragma unroll
            for (int mf = 0; mf < 2; ++mf)
                LDSM4(Af[mf], sA + aoff + mf * 1280 + h * 32);
            #pragma unroll
            for (int nfp = 0; nfp < 4; ++nfp)
                LDSM4(Bf[nfp], sB + boff + nfp * 1280 + h * 32);
            #pragma unroll
            for (int mf = 0; mf < 2; ++mf)
                #pragma unroll
                for (int nfp = 0; nfp < 4; ++nfp) {
                    MMAH(acc[mf][nfp * 2],     Af[mf], Bf[nfp][0], Bf[nfp][1]);
                    MMAH(acc[mf][nfp * 2 + 1], Af[mf], Bf[nfp][2], Bf[nfp][3]);
                }
        }
    }

    // epilogue
    int r = lane >> 2, q = lane & 3;
    size_t mr0 = m0 + warp_m * 32;
    int nc0 = warp_n * 64;
    #pragma unroll
    for (int mf = 0; mf < 2; ++mf) {
        size_t row = mr0 + mf * 16 + r;
        #pragma unroll
        for (int nf = 0; nf < 8; ++nf) {
            int col = nc0 + nf * 8 + q * 2;
            *reinterpret_cast<float2*>(out + row * 256 + col) =
                make_float2(acc[mf][nf][0], acc[mf][nf][1]);
            *reinterpret_cast<float2*>(out + (row + 8) * 256 + col) =
                make_float2(acc[mf][nf][2], acc[mf][nf][3]);
        }
    }
}

// ---------------------------------------------------------------------------
extern "C" void kernel_launch(void* const* d_in, const int* in_sizes, int n_in,
                              void* d_out, int out_size) {
    const float* x = (const float*)d_in[0];
    const float* coeffs = (const float*)d_in[1];
    const float* cs = (const float*)d_in[2];
    float* out = (float*)d_out;

    cudaFuncSetAttribute(yconv_kernel, cudaFuncAttributeMaxDynamicSharedMemorySize, 69632);
    cudaFuncSetAttribute(gemm_kernel, cudaFuncAttributeMaxDynamicSharedMemorySize, 122880);

    prep_kernel<<<640, 256>>>(coeffs);
    sconv_kernel<<<32768, 256>>>(x, cs);
    yconv_kernel<<<dim3(32, 64), 256, 69632>>>();
    gemm_kernel<<<2048, 512, 122880>>>(out);
}